// round 10
// baseline (speedup 1.0000x reference)
#include <cuda_runtime.h>
#include <math.h>

#define HH 1024
#define WW 1024
#define PLANES 24           // 8 batch * 3 channels
#define RAD 25
#define TAPS 51

#define XC 128              // output cols per block
#define YS 256              // output rows per block
#define NIT 39              // 8 H-rows per iter: rows 0..311 (need 306)
#define XW (XC + 2*RAD)     // 178 staged x cols
#define XP 184              // s_x pitch (floats), 16B-aligned rows
#define HB_ROWS 118         // 64-slot ring + 54-row mirror
#define MIRROR 54

// ---------------- compile-time gaussian weights -> FFMA immediates ----------
struct WTab { float w[TAPS]; };

__host__ __device__ constexpr double cexp_series(double x) {
    double term = 1.0, sum = 1.0;
    for (int i = 1; i < 40; ++i) { term *= x / (double)i; sum += term; }
    return sum;
}

__host__ __device__ constexpr WTab make_wtab() {
    WTab t{};
    double g[TAPS] = {};
    double s = 0.0;
    for (int i = 0; i < TAPS; ++i) {
        double d = (double)(i - RAD);
        g[i] = cexp_series(-d * d / (2.0 * 15.0 * 15.0));
        s += g[i];
    }
    for (int i = 0; i < TAPS; ++i) t.w[i] = (float)(g[i] / s);
    return t;
}

extern __shared__ float sm[];   // [ hb: 118*128 | s_x: 8*184 ] floats

__global__ void __launch_bounds__(256, 3) fused(const float* __restrict__ x,
                                                const float* __restrict__ amt_p,
                                                float* __restrict__ out) {
    float* hb = sm;                        // 118 x 128
    float* sx = sm + HB_ROWS * XC;         // 8 x 184

    const int t = threadIdx.x;
    const int plane = blockIdx.z;
    const int x0 = blockIdx.x * XC;
    const int yb = blockIdx.y * YS;
    const float* xp = x + (size_t)plane * HH * WW;
    float* op = out + (size_t)plane * HH * WW;

    const float kk = 1.2f * (0.4f / (1.0f + expf(-amt_p[0])));

    const int lr = t >> 5;                 // warp id = H row 0..7
    const int lc = t & 31;                 // lane
    const int vc = t & 127;                // V column
    const int vg = (t >> 7) << 2;          // V row group: 0 or 4

    constexpr WTab WT = make_wtab();

    // prefetch x rows for iter 0 into registers
    float px[6];
    {
        const int gy = yb - RAD + lr;
        const bool yok = ((unsigned)gy < HH);
        #pragma unroll
        for (int e = 0; e < 6; ++e) {
            const int c = lc + 32 * e;
            const int gx = x0 - RAD + c;
            px[e] = (yok && c < XW && (unsigned)gx < WW)
                    ? __ldg(&xp[(size_t)gy * WW + gx]) : 0.0f;
        }
    }

    #pragma unroll 1
    for (int i = 0; i < NIT; ++i) {
        // ---- stage prefetched x rows into s_x -------------------------------
        #pragma unroll
        for (int e = 0; e < 6; ++e) {
            const int c = lc + 32 * e;
            if (c < XP) sx[lr * XP + c] = px[e];
        }
        __syncthreads();   // s_x ready; V(i-1) finished reading hb

        // ---- prefetch x rows for iter i+1 (latency hidden under H+V) --------
        if (i + 1 < NIT) {
            const int gy = yb - RAD + 8 * (i + 1) + lr;
            const bool yok = ((unsigned)gy < HH);
            #pragma unroll
            for (int e = 0; e < 6; ++e) {
                const int c = lc + 32 * e;
                const int gx = x0 - RAD + c;
                px[e] = (yok && c < XW && (unsigned)gx < WW)
                        ? __ldg(&xp[(size_t)gy * WW + gx]) : 0.0f;
            }
        }

        // ---- H pass: warp lr does row lr, lane does 4 cols ------------------
        {
            const float4* row4 = reinterpret_cast<const float4*>(&sx[lr * XP]);
            float a0 = 0.f, a1 = 0.f, a2 = 0.f, a3 = 0.f;
            #pragma unroll
            for (int k4 = 0; k4 < 14; ++k4) {
                const float4 v4 = row4[lc + k4];       // consecutive lanes, no conflict
                const float vv[4] = {v4.x, v4.y, v4.z, v4.w};
                #pragma unroll
                for (int q = 0; q < 4; ++q) {
                    const int k = 4 * k4 + q;
                    if (k - 0 >= 0 && k - 0 <= 50) a0 += WT.w[k - 0] * vv[q];
                    if (k - 1 >= 0 && k - 1 <= 50) a1 += WT.w[k - 1] * vv[q];
                    if (k - 2 >= 0 && k - 2 <= 50) a2 += WT.w[k - 2] * vv[q];
                    if (k - 3 >= 0 && k - 3 <= 50) a3 += WT.w[k - 3] * vv[q];
                }
            }
            const int slot = (8 * i + lr) & 63;
            const float4 o = make_float4(a0, a1, a2, a3);
            *reinterpret_cast<float4*>(&hb[slot * XC + 4 * lc]) = o;
            if (slot < MIRROR)    // mirror so V reads are wrap-free linear
                *reinterpret_cast<float4*>(&hb[(slot + 64) * XC + 4 * lc]) = o;
        }
        __syncthreads();   // hb rows 8i..8i+7 visible to V

        // ---- V pass + screen blend (trails H by 7 iters) --------------------
        if (i >= 7) {
            const int vy0 = 8 * (i - 7) + vg;          // 4 output rows from vy0
            const float* vb = &hb[(vy0 & 63) * XC + vc];  // linear, imm offsets
            float a0 = 0.f, a1 = 0.f, a2 = 0.f, a3 = 0.f;
            #pragma unroll
            for (int dd = 0; dd < 54; ++dd) {
                const float v = vb[dd * XC];
                if (dd - 0 >= 0 && dd - 0 <= 50) a0 += WT.w[dd - 0] * v;
                if (dd - 1 >= 0 && dd - 1 <= 50) a1 += WT.w[dd - 1] * v;
                if (dd - 2 >= 0 && dd - 2 <= 50) a2 += WT.w[dd - 2] * v;
                if (dd - 3 >= 0 && dd - 3 <= 50) a3 += WT.w[dd - 3] * v;
            }
            const float av[4] = {a0, a1, a2, a3};
            #pragma unroll
            for (int o = 0; o < 4; ++o) {
                const size_t off = (size_t)(yb + vy0 + o) * WW + x0 + vc;
                const float xv = __ldg(&xp[off]);      // recent rows -> L2 hit
                float r = fmaf(av[o] * kk, 1.0f - xv, xv);
                op[off] = fminf(fmaxf(r, 0.0f), 1.0f);
            }
        }
    }
}

extern "C" void kernel_launch(void* const* d_in, const int* in_sizes, int n_in,
                              void* d_out, int out_size) {
    const float* x   = (const float*)d_in[0];
    const float* amt = (const float*)d_in[1];
    float* out = (float*)d_out;

    const int smem = (HB_ROWS * XC + 8 * XP) * (int)sizeof(float);  // 66304 B
    cudaFuncSetAttribute(fused, cudaFuncAttributeMaxDynamicSharedMemorySize, smem);

    dim3 grid(WW / XC, HH / YS, PLANES);   // (8, 4, 24) = 768 blocks
    fused<<<grid, 256, smem>>>(x, amt, out);
}